// round 14
// baseline (speedup 1.0000x reference)
#include <cuda_runtime.h>
#include <cstdint>

#define NNODES 100000
#define NEDGES 1600000
#define FDIM   64
#define KCHEB  6
#define NF     (NNODES * FDIM)
#define HALFB  128                      // bytes per half-row (32 floats)

// ---------------- scratch (device globals) ----------------------------------
__device__ int   g_degi[NNODES];
__device__ float g_dis[NNODES];
__device__ int   g_rowptr[NNODES + 1];
__device__ int   g_cursor[NNODES];
__device__ unsigned long long g_edge[NEDGES];   // packed (w<<32 | col*256)
__device__ float g_T[5][NF];                    // T1..T5 (T0 = x input)

// ---------------- helpers ----------------------------------------------------
__device__ __forceinline__ float2 unpack2(unsigned long long u) {
    float2 v;
    asm("mov.b64 {%0, %1}, %2;" : "=f"(v.x), "=f"(v.y) : "l"(u));
    return v;
}
__device__ __forceinline__ void fma2(unsigned long long &acc, float t, unsigned long long w) {
    unsigned long long tt;
    asm("mov.b64 %0, {%1, %1};" : "=l"(tt) : "f"(t));
    asm("fma.rn.f32x2 %0, %1, %2, %0;" : "+l"(acc) : "l"(tt), "l"(w));
}

// ---------------- 1. degree count (int) --------------------------------------
__global__ void k_count(const int* __restrict__ ei) {
    int e = blockIdx.x * blockDim.x + threadIdx.x;
    if (e >= NEDGES) return;
    atomicAdd(&g_degi[ei[e]], 1);
}

// ---------------- 2. D^{-1/2} (grid-wide) -------------------------------------
__global__ void k_dis() {
    int i = blockIdx.x * blockDim.x + threadIdx.x;
    if (i >= NNODES) return;
    int d = g_degi[i];
    g_dis[i] = (d > 0) ? rsqrtf((float)d) : 0.0f;
}

// ---------------- 3. single-block chunked exclusive scan -> rowptr ------------
__global__ void __launch_bounds__(1024, 1) k_scan() {
    __shared__ int warpsum[32];
    int t = threadIdx.x;
    const int CH = (NNODES + 1023) / 1024;
    int base = t * CH;
    int sum = 0;
    for (int j = 0; j < CH; j++) {
        int i = base + j;
        if (i < NNODES) sum += g_degi[i];
    }
    int lane = t & 31, w = t >> 5;
    int v = sum;
    #pragma unroll
    for (int off = 1; off < 32; off <<= 1) {
        int u = __shfl_up_sync(0xffffffffu, v, off);
        if (lane >= off) v += u;
    }
    if (lane == 31) warpsum[w] = v;
    __syncthreads();
    if (w == 0) {
        int s = warpsum[lane];
        #pragma unroll
        for (int off = 1; off < 32; off <<= 1) {
            int u = __shfl_up_sync(0xffffffffu, s, off);
            if (lane >= off) s += u;
        }
        warpsum[lane] = s;
    }
    __syncthreads();
    int off = (v - sum) + (w ? warpsum[w - 1] : 0);   // exclusive prefix
    for (int j = 0; j < CH; j++) {
        int i = base + j;
        if (i < NNODES) {
            g_rowptr[i] = off;
            g_cursor[i] = 0;
            off += g_degi[i];
        }
    }
    if (t == 1023) g_rowptr[NNODES] = NEDGES;
}

// ---------------- 4. fill CSR records, 4 edges/thread (MLP) -------------------
__global__ void k_fill(const int* __restrict__ ei) {
    int t = blockIdx.x * blockDim.x + threadIdx.x;
    int e0 = t * 4;
    if (e0 >= NEDGES) return;
    int4 r4 = *(const int4*)(ei + e0);
    int4 c4 = *(const int4*)(ei + NEDGES + e0);
    float dr0 = g_dis[r4.x], dr1 = g_dis[r4.y], dr2 = g_dis[r4.z], dr3 = g_dis[r4.w];
    float dc0 = g_dis[c4.x], dc1 = g_dis[c4.y], dc2 = g_dis[c4.z], dc3 = g_dis[c4.w];
    int p0 = atomicAdd(&g_cursor[r4.x], 1);
    int p1 = atomicAdd(&g_cursor[r4.y], 1);
    int p2 = atomicAdd(&g_cursor[r4.z], 1);
    int p3 = atomicAdd(&g_cursor[r4.w], 1);
    g_edge[g_rowptr[r4.x] + p0] =
        ((unsigned long long)__float_as_uint(-dr0 * dc0) << 32) | (unsigned)(c4.x << 8);
    g_edge[g_rowptr[r4.y] + p1] =
        ((unsigned long long)__float_as_uint(-dr1 * dc1) << 32) | (unsigned)(c4.y << 8);
    g_edge[g_rowptr[r4.z] + p2] =
        ((unsigned long long)__float_as_uint(-dr2 * dc2) << 32) | (unsigned)(c4.z << 8);
    g_edge[g_rowptr[r4.w] + p3] =
        ((unsigned long long)__float_as_uint(-dr3 * dc3) << 32) | (unsigned)(c4.w << 8);
}

// ---------------- 5. half-feature gather: one 32-col chain at a time ----------
// dst[n,half] = scale*sum_e w*src[col,half] - prev[n,half]
// 16 lanes per node (float2 per lane = 32 cols), 2 nodes per warp, 8-deep batch.
__global__ void __launch_bounds__(256)
k_gather(const float* __restrict__ src, const float* __restrict__ prev,
         float* __restrict__ dst, float scale, int halfoff) {
    int gid = blockIdx.x * blockDim.x + threadIdx.x;
    int node = gid >> 4;
    if (node >= NNODES) return;
    int lane = gid & 15;
    const char* sb = (const char*)src + halfoff + lane * 8;
    int i = g_rowptr[node], end = g_rowptr[node + 1];
    float ax = 0.0f, ay = 0.0f;

    for (; i + 8 <= end; i += 8) {
        unsigned long long r[8];
        #pragma unroll
        for (int u = 0; u < 8; u++) r[u] = g_edge[i + u];
        float2 v[8];
        #pragma unroll
        for (int u = 0; u < 8; u++)
            v[u] = *(const float2*)(sb + (unsigned)r[u]);
        #pragma unroll
        for (int u = 0; u < 8; u++) {
            float w = __uint_as_float((unsigned)(r[u] >> 32));
            ax = fmaf(w, v[u].x, ax);
            ay = fmaf(w, v[u].y, ay);
        }
    }
    if (i + 4 <= end) {
        unsigned long long r[4];
        #pragma unroll
        for (int u = 0; u < 4; u++) r[u] = g_edge[i + u];
        float2 v[4];
        #pragma unroll
        for (int u = 0; u < 4; u++)
            v[u] = *(const float2*)(sb + (unsigned)r[u]);
        #pragma unroll
        for (int u = 0; u < 4; u++) {
            float w = __uint_as_float((unsigned)(r[u] >> 32));
            ax = fmaf(w, v[u].x, ax);
            ay = fmaf(w, v[u].y, ay);
        }
        i += 4;
    }
    for (; i < end; i++) {
        unsigned long long r = g_edge[i];
        float2 v = *(const float2*)(sb + (unsigned)r);
        float w = __uint_as_float((unsigned)(r >> 32));
        ax = fmaf(w, v.x, ax);
        ay = fmaf(w, v.y, ay);
    }

    const char* pb = (const char*)prev + (size_t)node * 256 + halfoff + lane * 8;
    char*       db = (char*)dst        + (size_t)node * 256 + halfoff + lane * 8;
    float2 o;
    if (prev) {
        float2 pv = *(const float2*)pb;
        o.x = scale * ax - pv.x;
        o.y = scale * ay - pv.y;
    } else {
        o.x = scale * ax;
        o.y = scale * ay;
    }
    *(float2*)db = o;
}

// ---------------- 6. fused: out = InstanceNorm(sum_k T_k @ W_k + b), ReLU ----
// v4: 512-thread block (16 warps), single shared W copy, per-k T staging.
#define FK_WARPS 16
#define FK_NPW   8
#define FK_NPB   (FK_WARPS * FK_NPW)     // 128 nodes per block
#define FK_THREADS (FK_WARPS * 32)       // 512

__global__ void __launch_bounds__(FK_THREADS, 1)
k_final(const float* __restrict__ x, const float* __restrict__ W,
        const float* __restrict__ b, float* __restrict__ out) {
    extern __shared__ float sm[];
    float* sW = sm;                                   // 6*64*64 = 24576 floats
    float* sT = sm + KCHEB * FDIM * FDIM;             // 16 warps * 8*64 = 8192
    float* sb = sT + FK_WARPS * FK_NPW * FDIM;        // 64 floats

    int tid = threadIdx.x;
    for (int i = tid; i < KCHEB * FDIM * FDIM / 4; i += FK_THREADS)
        ((float4*)sW)[i] = ((const float4*)W)[i];
    if (tid < FDIM) sb[tid] = b[tid];
    __syncthreads();

    int warp = tid >> 5, lane = tid & 31;
    int nbase = blockIdx.x * FK_NPB + warp * FK_NPW;
    float* sTw = sT + warp * (FK_NPW * FDIM);

    unsigned long long acc[FK_NPW];
    unsigned long long bias_u = *(const unsigned long long*)(sb + 2 * lane);
    #pragma unroll
    for (int j = 0; j < FK_NPW; j++) acc[j] = bias_u;

    #pragma unroll
    for (int k = 0; k < KCHEB; k++) {
        const float* Tsrc = (k == 0) ? x : g_T[k - 1];
        #pragma unroll
        for (int j = 0; j < FK_NPW; j++) {
            int n = nbase + j;
            if (n < NNODES) {
                float2 v = ((const float2*)(Tsrc + (size_t)n * FDIM))[lane];
                ((float2*)(sTw + j * FDIM))[lane] = v;
            }
        }
        __syncwarp();

        #pragma unroll 4
        for (int i0 = 0; i0 < FDIM; i0 += 4) {
            unsigned long long wv[4];
            #pragma unroll
            for (int u = 0; u < 4; u++)
                wv[u] = *(const unsigned long long*)(sW + ((k * FDIM + i0 + u) * FDIM) + 2 * lane);
            #pragma unroll
            for (int j = 0; j < FK_NPW; j++) {
                float4 t = *(const float4*)(sTw + j * FDIM + i0);
                fma2(acc[j], t.x, wv[0]);
                fma2(acc[j], t.y, wv[1]);
                fma2(acc[j], t.z, wv[2]);
                fma2(acc[j], t.w, wv[3]);
            }
        }
        __syncwarp();   // before next k's staging overwrites sTw
    }

    #pragma unroll
    for (int j = 0; j < FK_NPW; j++) {
        float2 y = unpack2(acc[j]);
        float s = y.x + y.y;
        float q = y.x * y.x + y.y * y.y;
        #pragma unroll
        for (int off = 16; off > 0; off >>= 1) {
            s += __shfl_xor_sync(0xffffffffu, s, off);
            q += __shfl_xor_sync(0xffffffffu, q, off);
        }
        float mean = s * (1.0f / FDIM);
        float var  = q * (1.0f / FDIM) - mean * mean;
        float rstd = rsqrtf(var + 1e-5f);
        float2 r;
        r.x = fmaxf((y.x - mean) * rstd, 0.0f);
        r.y = fmaxf((y.y - mean) * rstd, 0.0f);
        int n = nbase + j;
        if (n < NNODES)
            ((float2*)(out + (size_t)n * FDIM))[lane] = r;
    }
}

// ---------------- launch ------------------------------------------------------
extern "C" void kernel_launch(void* const* d_in, const int* in_sizes, int n_in,
                              void* d_out, int out_size) {
    const float* x  = (const float*)d_in[0];
    const int*   ei = (const int*)d_in[1];     // int32 edge_index
    const float* W  = (const float*)d_in[2];
    const float* b  = (const float*)d_in[3];
    float*       out = (float*)d_out;

    void* p_degi; cudaGetSymbolAddress(&p_degi, g_degi);
    void* p_T;    cudaGetSymbolAddress(&p_T, g_T);
    float* T = (float*)p_T;

    const int TB = 256;
    cudaMemsetAsync(p_degi, 0, NNODES * sizeof(int));
    k_count<<<(NEDGES + TB - 1) / TB, TB>>>(ei);
    k_dis  <<<(NNODES + TB - 1) / TB, TB>>>();
    k_scan <<<1, 1024>>>();
    k_fill <<<(NEDGES / 4 + TB - 1) / TB, TB>>>(ei);

    const int GG = (NNODES * 16 + TB - 1) / TB;
    float* T1 = T;
    float* T2 = T + (size_t)1 * NF;
    float* T3 = T + (size_t)2 * NF;
    float* T4 = T + (size_t)3 * NF;
    float* T5 = T + (size_t)4 * NF;

    // Chebyshev chain per half-column block (keeps whole chain L2-resident)
    for (int h = 0; h < 2; h++) {
        int ho = h * HALFB;
        k_gather<<<GG, TB>>>(x,  nullptr, T1, 1.0f, ho);
        k_gather<<<GG, TB>>>(T1, x,       T2, 2.0f, ho);
        k_gather<<<GG, TB>>>(T2, T1,      T3, 2.0f, ho);
        k_gather<<<GG, TB>>>(T3, T2,      T4, 2.0f, ho);
        k_gather<<<GG, TB>>>(T4, T3,      T5, 2.0f, ho);
    }

    int smem = (KCHEB * FDIM * FDIM + FK_WARPS * FK_NPW * FDIM + FDIM) * (int)sizeof(float);
    cudaFuncSetAttribute(k_final, cudaFuncAttributeMaxDynamicSharedMemorySize, smem);
    k_final<<<(NNODES + FK_NPB - 1) / FK_NPB, FK_THREADS, smem>>>(x, W, b, out);
}

// round 15
// speedup vs baseline: 1.5674x; 1.5674x over previous
#include <cuda_runtime.h>
#include <cstdint>

#define NNODES 100000
#define NEDGES 1600000
#define FDIM   64
#define KCHEB  6
#define NF     (NNODES * FDIM)
#define SCH    1024                          // nodes per scan chunk
#define NCHUNK ((NNODES + SCH - 1) / SCH)    // 98

// ---------------- scratch (device globals) ----------------------------------
__device__ int   g_degi[NNODES];
__device__ float g_dis[NNODES];
__device__ int   g_rowptr[NNODES + 1];
__device__ int   g_cursor[NNODES];
__device__ int   g_csum[128];
__device__ int   g_coff[128];
__device__ unsigned long long g_edge[NEDGES];   // packed (w<<32 | col*256)
__device__ float g_T[5][NF];                    // T1..T5 (T0 = x input)

// ---------------- helpers ----------------------------------------------------
__device__ __forceinline__ float2 unpack2(unsigned long long u) {
    float2 v;
    asm("mov.b64 {%0, %1}, %2;" : "=f"(v.x), "=f"(v.y) : "l"(u));
    return v;
}
__device__ __forceinline__ void fma2(unsigned long long &acc, float t, unsigned long long w) {
    unsigned long long tt;
    asm("mov.b64 %0, {%1, %1};" : "=l"(tt) : "f"(t));
    asm("fma.rn.f32x2 %0, %1, %2, %0;" : "+l"(acc) : "l"(tt), "l"(w));
}

// ---------------- 1. degree count (int) --------------------------------------
__global__ void k_count(const int* __restrict__ ei) {
    int e = blockIdx.x * blockDim.x + threadIdx.x;
    if (e >= NEDGES) return;
    atomicAdd(&g_degi[ei[e]], 1);
}

// ---------------- 2. D^{-1/2} (grid-wide) -------------------------------------
__global__ void k_dis() {
    int i = blockIdx.x * blockDim.x + threadIdx.x;
    if (i >= NNODES) return;
    int d = g_degi[i];
    g_dis[i] = (d > 0) ? rsqrtf((float)d) : 0.0f;
}

// ---------------- 3a. per-chunk degree sums (grid-wide) -----------------------
__global__ void k_csumk() {
    __shared__ int ws[8];
    int t = threadIdx.x;
    int base = blockIdx.x * SCH + t * 4;
    int s = 0;
    #pragma unroll
    for (int j = 0; j < 4; j++) {
        int i = base + j;
        if (i < NNODES) s += g_degi[i];
    }
    #pragma unroll
    for (int off = 16; off > 0; off >>= 1)
        s += __shfl_down_sync(0xffffffffu, s, off);
    if ((t & 31) == 0) ws[t >> 5] = s;
    __syncthreads();
    if (t == 0) {
        int tot = 0;
        #pragma unroll
        for (int u = 0; u < 8; u++) tot += ws[u];
        g_csum[blockIdx.x] = tot;
    }
}

// ---------------- 3b. scan the 98 chunk sums (1 small block) ------------------
__global__ void k_cscan() {
    __shared__ int sh[128];
    int t = threadIdx.x;
    int v = (t < NCHUNK) ? g_csum[t] : 0;
    sh[t] = v;
    __syncthreads();
    #pragma unroll
    for (int off = 1; off < 128; off <<= 1) {
        int u = (t >= off) ? sh[t - off] : 0;
        __syncthreads();
        sh[t] += u;
        __syncthreads();
    }
    if (t < NCHUNK) g_coff[t] = sh[t] - v;     // exclusive prefix
}

// ---------------- 3c. rowptr scatter per chunk (grid-wide) --------------------
__global__ void k_rowptrk() {
    __shared__ int wsum[8];
    int t = threadIdx.x;
    int lane = t & 31, w = t >> 5;
    int base = blockIdx.x * SCH + t * 4;
    int d[4];
    int s = 0;
    #pragma unroll
    for (int j = 0; j < 4; j++) {
        int i = base + j;
        d[j] = (i < NNODES) ? g_degi[i] : 0;
        s += d[j];
    }
    int inc = s;
    #pragma unroll
    for (int off = 1; off < 32; off <<= 1) {
        int u = __shfl_up_sync(0xffffffffu, inc, off);
        if (lane >= off) inc += u;
    }
    if (lane == 31) wsum[w] = inc;
    __syncthreads();
    if (t == 0) {
        int r = 0;
        #pragma unroll
        for (int u = 0; u < 8; u++) { int x = wsum[u]; wsum[u] = r; r += x; }
    }
    __syncthreads();
    int off0 = (inc - s) + wsum[w] + g_coff[blockIdx.x];
    #pragma unroll
    for (int j = 0; j < 4; j++) {
        int i = base + j;
        if (i < NNODES) {
            g_rowptr[i] = off0;
            g_cursor[i] = 0;
            off0 += d[j];
        }
    }
    if (blockIdx.x == 0 && t == 0) g_rowptr[NNODES] = NEDGES;
}

// ---------------- 4. fill CSR records (col byte-offset, w) --------------------
__global__ void k_fill(const int* __restrict__ ei) {
    int e = blockIdx.x * blockDim.x + threadIdx.x;
    if (e >= NEDGES) return;
    int r = ei[e];
    int c = ei[NEDGES + e];
    float w = -g_dis[r] * g_dis[c];
    int pos = atomicAdd(&g_cursor[r], 1);
    unsigned long long rec = ((unsigned long long)__float_as_uint(w) << 32)
                           | (unsigned)(c << 8);           // pre-scaled byte offset
    g_edge[g_rowptr[r] + pos] = rec;
}

// ---------------- 5. gather prop: dst[n] = scale*sum_e w*src[col] - prev[n] ---
// 16 lanes per node (float4 per lane), 2 nodes per warp, 8-deep batch.
__global__ void __launch_bounds__(256)
k_gather(const float* __restrict__ src, const float* __restrict__ prev,
         float* __restrict__ dst, float scale) {
    int gid = blockIdx.x * blockDim.x + threadIdx.x;
    int node = gid >> 4;
    if (node >= NNODES) return;
    int lane = gid & 15;
    const char* sb = (const char*)src + lane * 16;
    int i = g_rowptr[node], end = g_rowptr[node + 1];
    float4 acc = make_float4(0.0f, 0.0f, 0.0f, 0.0f);

    for (; i + 8 <= end; i += 8) {
        unsigned long long r[8];
        #pragma unroll
        for (int u = 0; u < 8; u++) r[u] = g_edge[i + u];
        float4 v[8];
        #pragma unroll
        for (int u = 0; u < 8; u++)
            v[u] = *(const float4*)(sb + (unsigned)r[u]);
        #pragma unroll
        for (int u = 0; u < 8; u++) {
            float w = __uint_as_float((unsigned)(r[u] >> 32));
            acc.x = fmaf(w, v[u].x, acc.x);
            acc.y = fmaf(w, v[u].y, acc.y);
            acc.z = fmaf(w, v[u].z, acc.z);
            acc.w = fmaf(w, v[u].w, acc.w);
        }
    }
    if (i + 4 <= end) {
        unsigned long long r[4];
        #pragma unroll
        for (int u = 0; u < 4; u++) r[u] = g_edge[i + u];
        float4 v[4];
        #pragma unroll
        for (int u = 0; u < 4; u++)
            v[u] = *(const float4*)(sb + (unsigned)r[u]);
        #pragma unroll
        for (int u = 0; u < 4; u++) {
            float w = __uint_as_float((unsigned)(r[u] >> 32));
            acc.x = fmaf(w, v[u].x, acc.x);
            acc.y = fmaf(w, v[u].y, acc.y);
            acc.z = fmaf(w, v[u].z, acc.z);
            acc.w = fmaf(w, v[u].w, acc.w);
        }
        i += 4;
    }
    for (; i < end; i++) {
        unsigned long long r = g_edge[i];
        float4 v = *(const float4*)(sb + (unsigned)r);
        float w = __uint_as_float((unsigned)(r >> 32));
        acc.x = fmaf(w, v.x, acc.x);
        acc.y = fmaf(w, v.y, acc.y);
        acc.z = fmaf(w, v.z, acc.z);
        acc.w = fmaf(w, v.w, acc.w);
    }

    float4 o;
    if (prev) {
        float4 pv = ((const float4*)(prev + (size_t)node * FDIM))[lane];
        o.x = scale * acc.x - pv.x;
        o.y = scale * acc.y - pv.y;
        o.z = scale * acc.z - pv.z;
        o.w = scale * acc.w - pv.w;
    } else {
        o.x = scale * acc.x;
        o.y = scale * acc.y;
        o.z = scale * acc.z;
        o.w = scale * acc.w;
    }
    ((float4*)(dst + (size_t)node * FDIM))[lane] = o;
}

// ---------------- 6. fused: out = InstanceNorm(sum_k T_k @ W_k + b), ReLU ----
// v4: 512-thread block (16 warps), single shared W copy, per-k T staging.
#define FK_WARPS 16
#define FK_NPW   8
#define FK_NPB   (FK_WARPS * FK_NPW)     // 128 nodes per block
#define FK_THREADS (FK_WARPS * 32)       // 512

__global__ void __launch_bounds__(FK_THREADS, 1)
k_final(const float* __restrict__ x, const float* __restrict__ W,
        const float* __restrict__ b, float* __restrict__ out) {
    extern __shared__ float sm[];
    float* sW = sm;                                   // 6*64*64 = 24576 floats
    float* sT = sm + KCHEB * FDIM * FDIM;             // 16 warps * 8*64 = 8192
    float* sb = sT + FK_WARPS * FK_NPW * FDIM;        // 64 floats

    int tid = threadIdx.x;
    for (int i = tid; i < KCHEB * FDIM * FDIM / 4; i += FK_THREADS)
        ((float4*)sW)[i] = ((const float4*)W)[i];
    if (tid < FDIM) sb[tid] = b[tid];
    __syncthreads();

    int warp = tid >> 5, lane = tid & 31;
    int nbase = blockIdx.x * FK_NPB + warp * FK_NPW;
    float* sTw = sT + warp * (FK_NPW * FDIM);

    unsigned long long acc[FK_NPW];
    unsigned long long bias_u = *(const unsigned long long*)(sb + 2 * lane);
    #pragma unroll
    for (int j = 0; j < FK_NPW; j++) acc[j] = bias_u;

    #pragma unroll
    for (int k = 0; k < KCHEB; k++) {
        const float* Tsrc = (k == 0) ? x : g_T[k - 1];
        #pragma unroll
        for (int j = 0; j < FK_NPW; j++) {
            int n = nbase + j;
            if (n < NNODES) {
                float2 v = ((const float2*)(Tsrc + (size_t)n * FDIM))[lane];
                ((float2*)(sTw + j * FDIM))[lane] = v;
            }
        }
        __syncwarp();

        #pragma unroll 4
        for (int i0 = 0; i0 < FDIM; i0 += 4) {
            unsigned long long wv[4];
            #pragma unroll
            for (int u = 0; u < 4; u++)
                wv[u] = *(const unsigned long long*)(sW + ((k * FDIM + i0 + u) * FDIM) + 2 * lane);
            #pragma unroll
            for (int j = 0; j < FK_NPW; j++) {
                float4 t = *(const float4*)(sTw + j * FDIM + i0);
                fma2(acc[j], t.x, wv[0]);
                fma2(acc[j], t.y, wv[1]);
                fma2(acc[j], t.z, wv[2]);
                fma2(acc[j], t.w, wv[3]);
            }
        }
        __syncwarp();   // before next k's staging overwrites sTw
    }

    #pragma unroll
    for (int j = 0; j < FK_NPW; j++) {
        float2 y = unpack2(acc[j]);
        float s = y.x + y.y;
        float q = y.x * y.x + y.y * y.y;
        #pragma unroll
        for (int off = 16; off > 0; off >>= 1) {
            s += __shfl_xor_sync(0xffffffffu, s, off);
            q += __shfl_xor_sync(0xffffffffu, q, off);
        }
        float mean = s * (1.0f / FDIM);
        float var  = q * (1.0f / FDIM) - mean * mean;
        float rstd = rsqrtf(var + 1e-5f);
        float2 r;
        r.x = fmaxf((y.x - mean) * rstd, 0.0f);
        r.y = fmaxf((y.y - mean) * rstd, 0.0f);
        int n = nbase + j;
        if (n < NNODES)
            ((float2*)(out + (size_t)n * FDIM))[lane] = r;
    }
}

// ---------------- launch ------------------------------------------------------
extern "C" void kernel_launch(void* const* d_in, const int* in_sizes, int n_in,
                              void* d_out, int out_size) {
    const float* x  = (const float*)d_in[0];
    const int*   ei = (const int*)d_in[1];     // int32 edge_index
    const float* W  = (const float*)d_in[2];
    const float* b  = (const float*)d_in[3];
    float*       out = (float*)d_out;

    void* p_degi; cudaGetSymbolAddress(&p_degi, g_degi);
    void* p_T;    cudaGetSymbolAddress(&p_T, g_T);
    float* T = (float*)p_T;

    const int TB = 256;
    cudaMemsetAsync(p_degi, 0, NNODES * sizeof(int));
    k_count  <<<(NEDGES + TB - 1) / TB, TB>>>(ei);
    k_dis    <<<(NNODES + TB - 1) / TB, TB>>>();
    k_csumk  <<<NCHUNK, 256>>>();
    k_cscan  <<<1, 128>>>();
    k_rowptrk<<<NCHUNK, 256>>>();
    k_fill   <<<(NEDGES + TB - 1) / TB, TB>>>(ei);

    const int GG = (NNODES * 16 + TB - 1) / TB;
    float* T1 = T;
    float* T2 = T + (size_t)1 * NF;
    float* T3 = T + (size_t)2 * NF;
    float* T4 = T + (size_t)3 * NF;
    float* T5 = T + (size_t)4 * NF;

    k_gather<<<GG, TB>>>(x,  nullptr, T1, 1.0f);
    k_gather<<<GG, TB>>>(T1, x,       T2, 2.0f);
    k_gather<<<GG, TB>>>(T2, T1,      T3, 2.0f);
    k_gather<<<GG, TB>>>(T3, T2,      T4, 2.0f);
    k_gather<<<GG, TB>>>(T4, T3,      T5, 2.0f);

    int smem = (KCHEB * FDIM * FDIM + FK_WARPS * FK_NPW * FDIM + FDIM) * (int)sizeof(float);
    cudaFuncSetAttribute(k_final, cudaFuncAttributeMaxDynamicSharedMemorySize, smem);
    k_final<<<(NNODES + FK_NPB - 1) / FK_NPB, FK_THREADS, smem>>>(x, W, b, out);
}

// round 16
// speedup vs baseline: 1.5971x; 1.0189x over previous
#include <cuda_runtime.h>
#include <cstdint>

#define NNODES 100000
#define NEDGES 1600000
#define FDIM   64
#define KCHEB  6
#define NF     (NNODES * FDIM)
#define SCH    1024                          // nodes per scan chunk
#define NCHUNK ((NNODES + SCH - 1) / SCH)    // 98

// ---------------- scratch (device globals) ----------------------------------
__device__ int   g_degi[NNODES];
__device__ float g_dis[NNODES];
__device__ int   g_rowptr[NNODES + 1];
__device__ int   g_csum[128];
__device__ int   g_coff[128];
__device__ unsigned long long g_edge[NEDGES];   // packed (w<<32 | col*256)
__device__ float g_T[5][NF];                    // T1..T5 (T0 = x input)

// ---------------- helpers ----------------------------------------------------
__device__ __forceinline__ float2 unpack2(unsigned long long u) {
    float2 v;
    asm("mov.b64 {%0, %1}, %2;" : "=f"(v.x), "=f"(v.y) : "l"(u));
    return v;
}
__device__ __forceinline__ void fma2(unsigned long long &acc, float t, unsigned long long w) {
    unsigned long long tt;
    asm("mov.b64 %0, {%1, %1};" : "=l"(tt) : "f"(t));
    asm("fma.rn.f32x2 %0, %1, %2, %0;" : "+l"(acc) : "l"(tt), "l"(w));
}

// ---------------- 1. degree count (int) --------------------------------------
__global__ void k_count(const int* __restrict__ ei) {
    int e = blockIdx.x * blockDim.x + threadIdx.x;
    if (e >= NEDGES) return;
    atomicAdd(&g_degi[ei[e]], 1);
}

// ---------------- 2a. per-chunk degree sums + D^{-1/2} (both grid-wide) -------
__global__ void k_csumk() {
    __shared__ int ws[8];
    int t = threadIdx.x;
    int base = blockIdx.x * SCH + t * 4;
    int s = 0;
    #pragma unroll
    for (int j = 0; j < 4; j++) {
        int i = base + j;
        if (i < NNODES) {
            int d = g_degi[i];
            s += d;
            g_dis[i] = (d > 0) ? rsqrtf((float)d) : 0.0f;
        }
    }
    #pragma unroll
    for (int off = 16; off > 0; off >>= 1)
        s += __shfl_down_sync(0xffffffffu, s, off);
    if ((t & 31) == 0) ws[t >> 5] = s;
    __syncthreads();
    if (t == 0) {
        int tot = 0;
        #pragma unroll
        for (int u = 0; u < 8; u++) tot += ws[u];
        g_csum[blockIdx.x] = tot;
    }
}

// ---------------- 2b. scan the 98 chunk sums (1 small block) ------------------
__global__ void k_cscan() {
    __shared__ int sh[128];
    int t = threadIdx.x;
    int v = (t < NCHUNK) ? g_csum[t] : 0;
    sh[t] = v;
    __syncthreads();
    #pragma unroll
    for (int off = 1; off < 128; off <<= 1) {
        int u = (t >= off) ? sh[t - off] : 0;
        __syncthreads();
        sh[t] += u;
        __syncthreads();
    }
    if (t < NCHUNK) g_coff[t] = sh[t] - v;     // exclusive prefix
}

// ---------------- 2c. rowptr scatter per chunk (grid-wide) --------------------
__global__ void k_rowptrk() {
    __shared__ int wsum[8];
    int t = threadIdx.x;
    int lane = t & 31, w = t >> 5;
    int base = blockIdx.x * SCH + t * 4;
    int d[4];
    int s = 0;
    #pragma unroll
    for (int j = 0; j < 4; j++) {
        int i = base + j;
        d[j] = (i < NNODES) ? g_degi[i] : 0;
        s += d[j];
    }
    int inc = s;
    #pragma unroll
    for (int off = 1; off < 32; off <<= 1) {
        int u = __shfl_up_sync(0xffffffffu, inc, off);
        if (lane >= off) inc += u;
    }
    if (lane == 31) wsum[w] = inc;
    __syncthreads();
    if (t == 0) {
        int r = 0;
        #pragma unroll
        for (int u = 0; u < 8; u++) { int x = wsum[u]; wsum[u] = r; r += x; }
    }
    __syncthreads();
    int off0 = (inc - s) + wsum[w] + g_coff[blockIdx.x];
    #pragma unroll
    for (int j = 0; j < 4; j++) {
        int i = base + j;
        if (i < NNODES) {
            g_rowptr[i] = off0;
            off0 += d[j];
        }
    }
    if (blockIdx.x == 0 && t == 0) g_rowptr[NNODES] = NEDGES;
}

// ---------------- 3. fill CSR records; rowptr doubles as cursor ---------------
// atomicAdd(&rowptr[r],1) returns the slot. Afterwards rowptr[n] == old
// rowptr[n+1], so consumers use [n ? rowptr[n-1] : 0, rowptr[n]).
__global__ void k_fill(const int* __restrict__ ei) {
    int e = blockIdx.x * blockDim.x + threadIdx.x;
    if (e >= NEDGES) return;
    int r = ei[e];
    int c = ei[NEDGES + e];
    float w = -g_dis[r] * g_dis[c];
    int pos = atomicAdd(&g_rowptr[r], 1);
    unsigned long long rec = ((unsigned long long)__float_as_uint(w) << 32)
                           | (unsigned)(c << 8);           // pre-scaled byte offset
    g_edge[pos] = rec;
}

// ---------------- 4. gather prop: dst[n] = scale*sum_e w*src[col] - prev[n] ---
// 16 lanes per node (float4 per lane), 2 nodes per warp, 8-deep batch.
__global__ void __launch_bounds__(256)
k_gather(const float* __restrict__ src, const float* __restrict__ prev,
         float* __restrict__ dst, float scale) {
    int gid = blockIdx.x * blockDim.x + threadIdx.x;
    int node = gid >> 4;
    if (node >= NNODES) return;
    int lane = gid & 15;
    const char* sb = (const char*)src + lane * 16;
    int i = (node == 0) ? 0 : g_rowptr[node - 1];   // shifted rowptr (see k_fill)
    int end = g_rowptr[node];
    float4 acc = make_float4(0.0f, 0.0f, 0.0f, 0.0f);

    for (; i + 8 <= end; i += 8) {
        unsigned long long r[8];
        #pragma unroll
        for (int u = 0; u < 8; u++) r[u] = g_edge[i + u];
        float4 v[8];
        #pragma unroll
        for (int u = 0; u < 8; u++)
            v[u] = *(const float4*)(sb + (unsigned)r[u]);
        #pragma unroll
        for (int u = 0; u < 8; u++) {
            float w = __uint_as_float((unsigned)(r[u] >> 32));
            acc.x = fmaf(w, v[u].x, acc.x);
            acc.y = fmaf(w, v[u].y, acc.y);
            acc.z = fmaf(w, v[u].z, acc.z);
            acc.w = fmaf(w, v[u].w, acc.w);
        }
    }
    if (i + 4 <= end) {
        unsigned long long r[4];
        #pragma unroll
        for (int u = 0; u < 4; u++) r[u] = g_edge[i + u];
        float4 v[4];
        #pragma unroll
        for (int u = 0; u < 4; u++)
            v[u] = *(const float4*)(sb + (unsigned)r[u]);
        #pragma unroll
        for (int u = 0; u < 4; u++) {
            float w = __uint_as_float((unsigned)(r[u] >> 32));
            acc.x = fmaf(w, v[u].x, acc.x);
            acc.y = fmaf(w, v[u].y, acc.y);
            acc.z = fmaf(w, v[u].z, acc.z);
            acc.w = fmaf(w, v[u].w, acc.w);
        }
        i += 4;
    }
    for (; i < end; i++) {
        unsigned long long r = g_edge[i];
        float4 v = *(const float4*)(sb + (unsigned)r);
        float w = __uint_as_float((unsigned)(r >> 32));
        acc.x = fmaf(w, v.x, acc.x);
        acc.y = fmaf(w, v.y, acc.y);
        acc.z = fmaf(w, v.z, acc.z);
        acc.w = fmaf(w, v.w, acc.w);
    }

    float4 o;
    if (prev) {
        float4 pv = ((const float4*)(prev + (size_t)node * FDIM))[lane];
        o.x = scale * acc.x - pv.x;
        o.y = scale * acc.y - pv.y;
        o.z = scale * acc.z - pv.z;
        o.w = scale * acc.w - pv.w;
    } else {
        o.x = scale * acc.x;
        o.y = scale * acc.y;
        o.z = scale * acc.z;
        o.w = scale * acc.w;
    }
    ((float4*)(dst + (size_t)node * FDIM))[lane] = o;
}

// ---------------- 5. fused: out = InstanceNorm(sum_k T_k @ W_k + b), ReLU ----
// v4: 512-thread block (16 warps), single shared W copy, per-k T staging.
#define FK_WARPS 16
#define FK_NPW   8
#define FK_NPB   (FK_WARPS * FK_NPW)     // 128 nodes per block
#define FK_THREADS (FK_WARPS * 32)       // 512

__global__ void __launch_bounds__(FK_THREADS, 1)
k_final(const float* __restrict__ x, const float* __restrict__ W,
        const float* __restrict__ b, float* __restrict__ out) {
    extern __shared__ float sm[];
    float* sW = sm;                                   // 6*64*64 = 24576 floats
    float* sT = sm + KCHEB * FDIM * FDIM;             // 16 warps * 8*64 = 8192
    float* sb = sT + FK_WARPS * FK_NPW * FDIM;        // 64 floats

    int tid = threadIdx.x;
    for (int i = tid; i < KCHEB * FDIM * FDIM / 4; i += FK_THREADS)
        ((float4*)sW)[i] = ((const float4*)W)[i];
    if (tid < FDIM) sb[tid] = b[tid];
    __syncthreads();

    int warp = tid >> 5, lane = tid & 31;
    int nbase = blockIdx.x * FK_NPB + warp * FK_NPW;
    float* sTw = sT + warp * (FK_NPW * FDIM);

    unsigned long long acc[FK_NPW];
    unsigned long long bias_u = *(const unsigned long long*)(sb + 2 * lane);
    #pragma unroll
    for (int j = 0; j < FK_NPW; j++) acc[j] = bias_u;

    #pragma unroll
    for (int k = 0; k < KCHEB; k++) {
        const float* Tsrc = (k == 0) ? x : g_T[k - 1];
        #pragma unroll
        for (int j = 0; j < FK_NPW; j++) {
            int n = nbase + j;
            if (n < NNODES) {
                float2 v = ((const float2*)(Tsrc + (size_t)n * FDIM))[lane];
                ((float2*)(sTw + j * FDIM))[lane] = v;
            }
        }
        __syncwarp();

        #pragma unroll 4
        for (int i0 = 0; i0 < FDIM; i0 += 4) {
            unsigned long long wv[4];
            #pragma unroll
            for (int u = 0; u < 4; u++)
                wv[u] = *(const unsigned long long*)(sW + ((k * FDIM + i0 + u) * FDIM) + 2 * lane);
            #pragma unroll
            for (int j = 0; j < FK_NPW; j++) {
                float4 t = *(const float4*)(sTw + j * FDIM + i0);
                fma2(acc[j], t.x, wv[0]);
                fma2(acc[j], t.y, wv[1]);
                fma2(acc[j], t.z, wv[2]);
                fma2(acc[j], t.w, wv[3]);
            }
        }
        __syncwarp();   // before next k's staging overwrites sTw
    }

    #pragma unroll
    for (int j = 0; j < FK_NPW; j++) {
        float2 y = unpack2(acc[j]);
        float s = y.x + y.y;
        float q = y.x * y.x + y.y * y.y;
        #pragma unroll
        for (int off = 16; off > 0; off >>= 1) {
            s += __shfl_xor_sync(0xffffffffu, s, off);
            q += __shfl_xor_sync(0xffffffffu, q, off);
        }
        float mean = s * (1.0f / FDIM);
        float var  = q * (1.0f / FDIM) - mean * mean;
        float rstd = rsqrtf(var + 1e-5f);
        float2 r;
        r.x = fmaxf((y.x - mean) * rstd, 0.0f);
        r.y = fmaxf((y.y - mean) * rstd, 0.0f);
        int n = nbase + j;
        if (n < NNODES)
            ((float2*)(out + (size_t)n * FDIM))[lane] = r;
    }
}

// ---------------- launch ------------------------------------------------------
extern "C" void kernel_launch(void* const* d_in, const int* in_sizes, int n_in,
                              void* d_out, int out_size) {
    const float* x  = (const float*)d_in[0];
    const int*   ei = (const int*)d_in[1];     // int32 edge_index
    const float* W  = (const float*)d_in[2];
    const float* b  = (const float*)d_in[3];
    float*       out = (float*)d_out;

    void* p_degi; cudaGetSymbolAddress(&p_degi, g_degi);
    void* p_T;    cudaGetSymbolAddress(&p_T, g_T);
    float* T = (float*)p_T;

    const int TB = 256;
    cudaMemsetAsync(p_degi, 0, NNODES * sizeof(int));
    k_count  <<<(NEDGES + TB - 1) / TB, TB>>>(ei);
    k_csumk  <<<NCHUNK, 256>>>();
    k_cscan  <<<1, 128>>>();
    k_rowptrk<<<NCHUNK, 256>>>();
    k_fill   <<<(NEDGES + TB - 1) / TB, TB>>>(ei);

    const int GG = (NNODES * 16 + TB - 1) / TB;
    float* T1 = T;
    float* T2 = T + (size_t)1 * NF;
    float* T3 = T + (size_t)2 * NF;
    float* T4 = T + (size_t)3 * NF;
    float* T5 = T + (size_t)4 * NF;

    k_gather<<<GG, TB>>>(x,  nullptr, T1, 1.0f);
    k_gather<<<GG, TB>>>(T1, x,       T2, 2.0f);
    k_gather<<<GG, TB>>>(T2, T1,      T3, 2.0f);
    k_gather<<<GG, TB>>>(T3, T2,      T4, 2.0f);
    k_gather<<<GG, TB>>>(T4, T3,      T5, 2.0f);

    int smem = (KCHEB * FDIM * FDIM + FK_WARPS * FK_NPW * FDIM + FDIM) * (int)sizeof(float);
    cudaFuncSetAttribute(k_final, cudaFuncAttributeMaxDynamicSharedMemorySize, smem);
    k_final<<<(NNODES + FK_NPB - 1) / FK_NPB, FK_THREADS, smem>>>(x, W, b, out);
}

// round 17
// speedup vs baseline: 1.8243x; 1.1422x over previous
#include <cuda_runtime.h>
#include <cstdint>
#include <mma.h>

using namespace nvcuda;

#define NNODES 100000
#define NEDGES 1600000
#define FDIM   64
#define KCHEB  6
#define NF     (NNODES * FDIM)
#define SCH    1024                          // nodes per scan chunk
#define NCHUNK ((NNODES + SCH - 1) / SCH)    // 98

// ---------------- scratch (device globals) ----------------------------------
__device__ int   g_degi[NNODES];
__device__ float g_dis[NNODES];
__device__ int   g_rowptr[NNODES + 1];
__device__ int   g_csum[128];
__device__ int   g_coff[128];
__device__ float g_Wt[KCHEB * FDIM * FDIM];     // W pre-rounded to tf32 values
__device__ unsigned long long g_edge[NEDGES];   // packed (w<<32 | col*256)
__device__ float g_T[5][NF];                    // T1..T5 (T0 = x input)

// ---------------- 1. degree count (int) --------------------------------------
__global__ void k_count(const int* __restrict__ ei) {
    int e = blockIdx.x * blockDim.x + threadIdx.x;
    if (e >= NEDGES) return;
    atomicAdd(&g_degi[ei[e]], 1);
}

// ---------------- 2a. per-chunk degree sums + D^{-1/2} ------------------------
__global__ void k_csumk() {
    __shared__ int ws[8];
    int t = threadIdx.x;
    int base = blockIdx.x * SCH + t * 4;
    int s = 0;
    #pragma unroll
    for (int j = 0; j < 4; j++) {
        int i = base + j;
        if (i < NNODES) {
            int d = g_degi[i];
            s += d;
            g_dis[i] = (d > 0) ? rsqrtf((float)d) : 0.0f;
        }
    }
    #pragma unroll
    for (int off = 16; off > 0; off >>= 1)
        s += __shfl_down_sync(0xffffffffu, s, off);
    if ((t & 31) == 0) ws[t >> 5] = s;
    __syncthreads();
    if (t == 0) {
        int tot = 0;
        #pragma unroll
        for (int u = 0; u < 8; u++) tot += ws[u];
        g_csum[blockIdx.x] = tot;
    }
}

// ---------------- 2b. scan the 98 chunk sums (1 small block) ------------------
__global__ void k_cscan() {
    __shared__ int sh[128];
    int t = threadIdx.x;
    int v = (t < NCHUNK) ? g_csum[t] : 0;
    sh[t] = v;
    __syncthreads();
    #pragma unroll
    for (int off = 1; off < 128; off <<= 1) {
        int u = (t >= off) ? sh[t - off] : 0;
        __syncthreads();
        sh[t] += u;
        __syncthreads();
    }
    if (t < NCHUNK) g_coff[t] = sh[t] - v;     // exclusive prefix
}

// ---------------- 2c. rowptr scatter per chunk (grid-wide) --------------------
__global__ void k_rowptrk() {
    __shared__ int wsum[8];
    int t = threadIdx.x;
    int lane = t & 31, w = t >> 5;
    int base = blockIdx.x * SCH + t * 4;
    int d[4];
    int s = 0;
    #pragma unroll
    for (int j = 0; j < 4; j++) {
        int i = base + j;
        d[j] = (i < NNODES) ? g_degi[i] : 0;
        s += d[j];
    }
    int inc = s;
    #pragma unroll
    for (int off = 1; off < 32; off <<= 1) {
        int u = __shfl_up_sync(0xffffffffu, inc, off);
        if (lane >= off) inc += u;
    }
    if (lane == 31) wsum[w] = inc;
    __syncthreads();
    if (t == 0) {
        int r = 0;
        #pragma unroll
        for (int u = 0; u < 8; u++) { int x = wsum[u]; wsum[u] = r; r += x; }
    }
    __syncthreads();
    int off0 = (inc - s) + wsum[w] + g_coff[blockIdx.x];
    #pragma unroll
    for (int j = 0; j < 4; j++) {
        int i = base + j;
        if (i < NNODES) {
            g_rowptr[i] = off0;
            off0 += d[j];
        }
    }
    if (blockIdx.x == 0 && t == 0) g_rowptr[NNODES] = NEDGES;
}

// ---------------- 2d. pre-round W to tf32-exact values ------------------------
__global__ void k_wtf(const float* __restrict__ W) {
    int i = blockIdx.x * blockDim.x + threadIdx.x;
    if (i < KCHEB * FDIM * FDIM)
        g_Wt[i] = wmma::__float_to_tf32(W[i]);
}

// ---------------- 3. fill CSR records; rowptr doubles as cursor ---------------
__global__ void k_fill(const int* __restrict__ ei) {
    int e = blockIdx.x * blockDim.x + threadIdx.x;
    if (e >= NEDGES) return;
    int r = ei[e];
    int c = ei[NEDGES + e];
    float w = -g_dis[r] * g_dis[c];
    int pos = atomicAdd(&g_rowptr[r], 1);
    unsigned long long rec = ((unsigned long long)__float_as_uint(w) << 32)
                           | (unsigned)(c << 8);           // pre-scaled byte offset
    g_edge[pos] = rec;
}

// ---------------- 4. gather prop: dst[n] = scale*sum_e w*src[col] - prev[n] ---
__global__ void __launch_bounds__(256)
k_gather(const float* __restrict__ src, const float* __restrict__ prev,
         float* __restrict__ dst, float scale) {
    int gid = blockIdx.x * blockDim.x + threadIdx.x;
    int node = gid >> 4;
    if (node >= NNODES) return;
    int lane = gid & 15;
    const char* sb = (const char*)src + lane * 16;
    int i = (node == 0) ? 0 : g_rowptr[node - 1];   // shifted rowptr (see k_fill)
    int end = g_rowptr[node];
    float4 acc = make_float4(0.0f, 0.0f, 0.0f, 0.0f);

    for (; i + 8 <= end; i += 8) {
        unsigned long long r[8];
        #pragma unroll
        for (int u = 0; u < 8; u++) r[u] = g_edge[i + u];
        float4 v[8];
        #pragma unroll
        for (int u = 0; u < 8; u++)
            v[u] = *(const float4*)(sb + (unsigned)r[u]);
        #pragma unroll
        for (int u = 0; u < 8; u++) {
            float w = __uint_as_float((unsigned)(r[u] >> 32));
            acc.x = fmaf(w, v[u].x, acc.x);
            acc.y = fmaf(w, v[u].y, acc.y);
            acc.z = fmaf(w, v[u].z, acc.z);
            acc.w = fmaf(w, v[u].w, acc.w);
        }
    }
    if (i + 4 <= end) {
        unsigned long long r[4];
        #pragma unroll
        for (int u = 0; u < 4; u++) r[u] = g_edge[i + u];
        float4 v[4];
        #pragma unroll
        for (int u = 0; u < 4; u++)
            v[u] = *(const float4*)(sb + (unsigned)r[u]);
        #pragma unroll
        for (int u = 0; u < 4; u++) {
            float w = __uint_as_float((unsigned)(r[u] >> 32));
            acc.x = fmaf(w, v[u].x, acc.x);
            acc.y = fmaf(w, v[u].y, acc.y);
            acc.z = fmaf(w, v[u].z, acc.z);
            acc.w = fmaf(w, v[u].w, acc.w);
        }
        i += 4;
    }
    for (; i < end; i++) {
        unsigned long long r = g_edge[i];
        float4 v = *(const float4*)(sb + (unsigned)r);
        float w = __uint_as_float((unsigned)(r >> 32));
        acc.x = fmaf(w, v.x, acc.x);
        acc.y = fmaf(w, v.y, acc.y);
        acc.z = fmaf(w, v.z, acc.z);
        acc.w = fmaf(w, v.w, acc.w);
    }

    float4 o;
    if (prev) {
        float4 pv = ((const float4*)(prev + (size_t)node * FDIM))[lane];
        o.x = scale * acc.x - pv.x;
        o.y = scale * acc.y - pv.y;
        o.z = scale * acc.z - pv.z;
        o.w = scale * acc.w - pv.w;
    } else {
        o.x = scale * acc.x;
        o.y = scale * acc.y;
        o.z = scale * acc.z;
        o.w = scale * acc.w;
    }
    ((float4*)(dst + (size_t)node * FDIM))[lane] = o;
}

// ---------------- 5. fused GEMM (wmma tf32) + InstanceNorm + ReLU -------------
// 8 warps * 32 rows; m16n16k8 tf32 fragments; A converted in regs, W pre-rounded.
#define TC_WARPS 8
#define TC_RPW   32
#define TC_RPB   (TC_WARPS * TC_RPW)      // 256 rows per block

__global__ void __launch_bounds__(256, 2)
k_final(const float* __restrict__ x, const float* __restrict__ b,
        float* __restrict__ out) {
    extern __shared__ float sm[];                       // 8*32*64 stage + 64 bias
    float* sb = sm + TC_WARPS * TC_RPW * FDIM;

    int tid = threadIdx.x, warp = tid >> 5, lane = tid & 31;
    if (tid < FDIM) sb[tid] = b[tid];
    __syncthreads();

    float* stage = sm + warp * (TC_RPW * FDIM);
    int row0 = blockIdx.x * TC_RPB + warp * TC_RPW;
    // NNODES % 16 == 0: a 16-row tile is either fully in-bounds or fully out.
    int r0 = (row0      < NNODES) ? row0      : 0;
    int r1 = (row0 + 16 < NNODES) ? row0 + 16 : 0;

    wmma::fragment<wmma::accumulator, 16, 16, 8, float> acc[2][4];
    #pragma unroll
    for (int mi = 0; mi < 2; mi++)
        #pragma unroll
        for (int ni = 0; ni < 4; ni++)
            wmma::fill_fragment(acc[mi][ni], 0.0f);

    #pragma unroll
    for (int k = 0; k < KCHEB; k++) {
        const float* Ts = (k == 0) ? x : g_T[k - 1];
        const float* a0 = Ts + (size_t)r0 * FDIM;
        const float* a1 = Ts + (size_t)r1 * FDIM;
        #pragma unroll
        for (int kk = 0; kk < FDIM / 8; kk++) {
            wmma::fragment<wmma::matrix_a, 16, 16, 8, wmma::precision::tf32,
                           wmma::row_major> A0, A1;
            wmma::load_matrix_sync(A0, a0 + kk * 8, FDIM);
            wmma::load_matrix_sync(A1, a1 + kk * 8, FDIM);
            #pragma unroll
            for (int e = 0; e < A0.num_elements; e++) {
                A0.x[e] = wmma::__float_to_tf32(A0.x[e]);
                A1.x[e] = wmma::__float_to_tf32(A1.x[e]);
            }
            wmma::fragment<wmma::matrix_b, 16, 16, 8, wmma::precision::tf32,
                           wmma::row_major> B[4];
            #pragma unroll
            for (int ni = 0; ni < 4; ni++)
                wmma::load_matrix_sync(B[ni],
                    g_Wt + (k * FDIM + kk * 8) * FDIM + ni * 16, FDIM);
            #pragma unroll
            for (int ni = 0; ni < 4; ni++) {
                wmma::mma_sync(acc[0][ni], A0, B[ni], acc[0][ni]);
                wmma::mma_sync(acc[1][ni], A1, B[ni], acc[1][ni]);
            }
        }
    }

    // stage accumulators, then per-row InstanceNorm + ReLU
    #pragma unroll
    for (int mi = 0; mi < 2; mi++)
        #pragma unroll
        for (int ni = 0; ni < 4; ni++)
            wmma::store_matrix_sync(stage + mi * 16 * FDIM + ni * 16,
                                    acc[mi][ni], FDIM, wmma::mem_row_major);
    __syncwarp();

    float bx = sb[2 * lane], by = sb[2 * lane + 1];
    for (int j = 0; j < TC_RPW; j++) {
        int n = row0 + j;
        if (n >= NNODES) break;
        float2 y = ((const float2*)(stage + j * FDIM))[lane];
        y.x += bx;
        y.y += by;
        float s = y.x + y.y;
        float q = y.x * y.x + y.y * y.y;
        #pragma unroll
        for (int off = 16; off > 0; off >>= 1) {
            s += __shfl_xor_sync(0xffffffffu, s, off);
            q += __shfl_xor_sync(0xffffffffu, q, off);
        }
        float mean = s * (1.0f / FDIM);
        float var  = q * (1.0f / FDIM) - mean * mean;
        float rstd = rsqrtf(var + 1e-5f);
        float2 r;
        r.x = fmaxf((y.x - mean) * rstd, 0.0f);
        r.y = fmaxf((y.y - mean) * rstd, 0.0f);
        ((float2*)(out + (size_t)n * FDIM))[lane] = r;
    }
}

// ---------------- launch ------------------------------------------------------
extern "C" void kernel_launch(void* const* d_in, const int* in_sizes, int n_in,
                              void* d_out, int out_size) {
    const float* x  = (const float*)d_in[0];
    const int*   ei = (const int*)d_in[1];     // int32 edge_index
    const float* W  = (const float*)d_in[2];
    const float* b  = (const float*)d_in[3];
    float*       out = (float*)d_out;

    void* p_degi; cudaGetSymbolAddress(&p_degi, g_degi);
    void* p_T;    cudaGetSymbolAddress(&p_T, g_T);
    float* T = (float*)p_T;

    const int TB = 256;
    cudaMemsetAsync(p_degi, 0, NNODES * sizeof(int));
    k_count  <<<(NEDGES + TB - 1) / TB, TB>>>(ei);
    k_csumk  <<<NCHUNK, 256>>>();
    k_cscan  <<<1, 128>>>();
    k_rowptrk<<<NCHUNK, 256>>>();
    k_wtf    <<<(KCHEB * FDIM * FDIM + TB - 1) / TB, TB>>>(W);
    k_fill   <<<(NEDGES + TB - 1) / TB, TB>>>(ei);

    const int GG = (NNODES * 16 + TB - 1) / TB;
    float* T1 = T;
    float* T2 = T + (size_t)1 * NF;
    float* T3 = T + (size_t)2 * NF;
    float* T4 = T + (size_t)3 * NF;
    float* T5 = T + (size_t)4 * NF;

    k_gather<<<GG, TB>>>(x,  nullptr, T1, 1.0f);
    k_gather<<<GG, TB>>>(T1, x,       T2, 2.0f);
    k_gather<<<GG, TB>>>(T2, T1,      T3, 2.0f);
    k_gather<<<GG, TB>>>(T3, T2,      T4, 2.0f);
    k_gather<<<GG, TB>>>(T4, T3,      T5, 2.0f);

    int smem = (TC_WARPS * TC_RPW * FDIM + FDIM) * (int)sizeof(float);
    cudaFuncSetAttribute(k_final, cudaFuncAttributeMaxDynamicSharedMemorySize, smem);
    k_final<<<(NNODES + TC_RPB - 1) / TC_RPB, 256, smem>>>(x, b, out);
}